// round 15
// baseline (speedup 1.0000x reference)
#include <cuda_runtime.h>

#define NB 256
#define NT 64
#define ND 2048
#define NT_Q 16
#define NZ 4
#define THRESHOLD 0.99f
#define EPSILON 0.01f

// Partial accumulators for t-quarters 1..3 (z=0 writes final_out directly).
__device__ float g_partial[NZ - 1][NB * ND];   // 3 x 2 MB

// Fused kernel. grid = (4, NB, 4), block = 128 threads.
// Phase 1: warp 0 of every block computes ACT weights for batch b (warp scan).
//          Block (0, b, 0) also writes weights + ponder_cost to gmem.
// Phase 2: block z accumulates t in [z*16, z*16+16) for its D-chunk.
__global__ void __launch_bounds__(128) act_fused_kernel(
        const float* __restrict__ halt_probs,
        const float* __restrict__ outputs,
        const float* __restrict__ step_weights,
        float* __restrict__ final_out,
        float* __restrict__ ponder_out,
        float* __restrict__ weights_out) {
    __shared__ float wsh[NT];
    const int b = blockIdx.y;
    const int z = blockIdx.z;
    const unsigned FULL = 0xffffffffu;

    if (threadIdx.x < 32) {
        const int lane = threadIdx.x;
        const float* p  = halt_probs   + (size_t)b * NT;
        const float* sw = step_weights + (size_t)b * NT;

        float a = p[lane];          // t = lane
        float c = p[lane + 32];     // t = lane + 32

        // Inclusive scan over 64 elements (two 32-lane halves).
        float sa = a;
        #pragma unroll
        for (int off = 1; off < 32; off <<= 1) {
            float v = __shfl_up_sync(FULL, sa, off);
            if (lane >= off) sa += v;
        }
        float tot_a = __shfl_sync(FULL, sa, 31);
        float sc = c;
        #pragma unroll
        for (int off = 1; off < 32; off <<= 1) {
            float v = __shfl_up_sync(FULL, sc, off);
            if (lane >= off) sc += v;
        }
        sc += tot_a;

        // First t with cumsum >= THRESHOLD (fallback T-1).
        unsigned m1 = __ballot_sync(FULL, sa >= THRESHOLD);
        unsigned m2 = __ballot_sync(FULL, sc >= THRESHOLD);
        int h;
        if (m1)      h = __ffs(m1) - 1;
        else if (m2) h = 32 + __ffs(m2) - 1;
        else         h = NT - 1;

        float cum_at, p_at;
        if (h < 32) {
            cum_at = __shfl_sync(FULL, sa, h);
            p_at   = __shfl_sync(FULL, a,  h);
        } else {
            cum_at = __shfl_sync(FULL, sc, h - 32);
            p_at   = __shfl_sync(FULL, c,  h - 32);
        }
        float remaining = 1.0f - cum_at + p_at;

        float sw_a = sw[lane], sw_c = sw[lane + 32];
        int t0 = lane, t1 = lane + 32;
        float w0 = (t0 < h) ? a : ((t0 == h) ? remaining : 0.0f);
        float w1 = (t1 < h) ? c : ((t1 == h) ? remaining : 0.0f);
        w0 *= sw_a;
        w1 *= sw_c;

        float s = w0 + w1;
        #pragma unroll
        for (int off = 16; off > 0; off >>= 1)
            s += __shfl_xor_sync(FULL, s, off);
        float inv = 1.0f / fmaxf(s, EPSILON);

        w0 *= inv;
        w1 *= inv;
        wsh[t0] = w0;
        wsh[t1] = w1;

        if (blockIdx.x == 0 && z == 0) {
            weights_out[(size_t)b * NT + t0] = w0;
            weights_out[(size_t)b * NT + t1] = w1;
            float pc = w0 * (float)(t0 + 1) + w1 * (float)(t1 + 1);
            #pragma unroll
            for (int off = 16; off > 0; off >>= 1)
                pc += __shfl_xor_sync(FULL, pc, off);
            if (lane == 0) ponder_out[b] = pc;
        }
    }
    __syncthreads();

    // Phase 2: thread owns one float4 lane of D; t-range [z*16, z*16+16).
    const int idx = blockIdx.x * blockDim.x + threadIdx.x;   // float4 index in D
    const int row4 = ND / 4;
    const int tbase = z * NT_Q;
    const float4* src = (const float4*)(outputs + (size_t)b * NT * ND)
                        + (size_t)tbase * row4 + idx;

    float4 acc = make_float4(0.f, 0.f, 0.f, 0.f);
    #pragma unroll
    for (int tb = 0; tb < NT_Q; tb += 8) {
        float4 v[8];
        #pragma unroll
        for (int i = 0; i < 8; i++)
            v[i] = __ldcs(src + (size_t)(tb + i) * row4);
        #pragma unroll
        for (int i = 0; i < 8; i++) {
            float wt = wsh[tbase + tb + i];
            acc.x = fmaf(wt, v[i].x, acc.x);
            acc.y = fmaf(wt, v[i].y, acc.y);
            acc.z = fmaf(wt, v[i].z, acc.z);
            acc.w = fmaf(wt, v[i].w, acc.w);
        }
    }

    float4* dst = (z == 0) ? (float4*)(final_out + (size_t)b * ND)
                           : (float4*)(g_partial[z - 1] + (size_t)b * ND);
    dst[idx] = acc;
}

// Combine: final_out += sum of 3 partials. 131072 float4 positions.
// grid = 128 x 256 threads, 4 positions per thread, 16 batched loads (MLP=16).
#define CMB_THREADS 32768
__global__ void __launch_bounds__(256) act_combine_kernel(float* __restrict__ final_out) {
    const int tid = blockIdx.x * blockDim.x + threadIdx.x;
    float4* dst = (float4*)final_out;
    const float4* p0 = (const float4*)g_partial[0];
    const float4* p1 = (const float4*)g_partial[1];
    const float4* p2 = (const float4*)g_partial[2];

    float4 f[4], a[4], c[4], d[4];
    #pragma unroll
    for (int k = 0; k < 4; k++) {
        int i = tid + k * CMB_THREADS;
        f[k] = dst[i]; a[k] = p0[i]; c[k] = p1[i]; d[k] = p2[i];
    }
    #pragma unroll
    for (int k = 0; k < 4; k++) {
        int i = tid + k * CMB_THREADS;
        float4 r;
        r.x = f[k].x + a[k].x + c[k].x + d[k].x;
        r.y = f[k].y + a[k].y + c[k].y + d[k].y;
        r.z = f[k].z + a[k].z + c[k].z + d[k].z;
        r.w = f[k].w + a[k].w + c[k].w + d[k].w;
        dst[i] = r;
    }
}

extern "C" void kernel_launch(void* const* d_in, const int* in_sizes, int n_in,
                              void* d_out, int out_size) {
    const float* halt_probs   = (const float*)d_in[0];  // [B, T, 1]
    const float* outputs      = (const float*)d_in[1];  // [B, T, D]
    const float* step_weights = (const float*)d_in[2];  // [B, T]

    float* final_out   = (float*)d_out;                 // [B, D]
    float* ponder_out  = final_out + (size_t)NB * ND;   // [B]
    float* weights_out = ponder_out + NB;               // [B, T]

    dim3 grid(ND / (128 * 4), NB, NZ);                  // (4, 256, 4)
    act_fused_kernel<<<grid, 128>>>(halt_probs, outputs, step_weights,
                                    final_out, ponder_out, weights_out);

    act_combine_kernel<<<CMB_THREADS / 256, 256>>>(final_out);
}